// round 1
// baseline (speedup 1.0000x reference)
#include <cuda_runtime.h>
#include <cstdint>

#define OUT_F   11008
#define IN_F    4096
#define BATCH   32
#define GROUP   128

#define KC      64                  // k-chunk per smem stage
#define OT      64                  // outputs per block
#define KSPLIT  2
#define KRANGE  (IN_F / KSPLIT)     // 2048
#define OGROUPS (OUT_F / OT)        // 172
#define THREADS 256
#define XSTRIDE (KC + 4)            // 68 floats: 272B row stride -> conflict-free LDS.128

// Packed f32x2 FMA (Blackwell): d = a*b + d on two fp32 lanes at once.
__device__ __forceinline__ void fma2(unsigned long long &d,
                                     unsigned long long a,
                                     unsigned long long b) {
    asm("fma.rn.f32x2 %0, %1, %2, %0;" : "+l"(d) : "l"(a), "l"(b));
}

__device__ __forceinline__ float hsum2(unsigned long long v) {
    float lo, hi;
    asm("mov.b64 {%0, %1}, %2;" : "=f"(lo), "=f"(hi) : "l"(v));
    return lo + hi;
}

__global__ void init_out_kernel(const float* __restrict__ bias,
                                float* __restrict__ out) {
    int i = blockIdx.x * blockDim.x + threadIdx.x;
    if (i < BATCH * OUT_F) {
        out[i] = bias[i % OUT_F];
    }
}

__global__ __launch_bounds__(THREADS, 3)
void wql_kernel(const float* __restrict__ x,
                const int*   __restrict__ pw,
                const float* __restrict__ scale,
                float*       __restrict__ out) {
    __shared__ float xtile[BATCH * XSTRIDE];   // 8704 B
    __shared__ float wtile[OT * KC];           // 16384 B

    const int bid   = blockIdx.x;
    const int og    = bid % OGROUPS;           // output group
    const int ks    = bid / OGROUPS;           // k split
    const int tid   = threadIdx.x;
    const int lane  = tid & 31;                // = batch index
    const int warp  = tid >> 5;                // 8 warps, 8 outputs each
    const int obase = og * OT;

    unsigned long long accA[8], accB[8];
#pragma unroll
    for (int i = 0; i < 8; ++i) { accA[i] = 0ull; accB[i] = 0ull; }

    const int kbase = ks * KRANGE;

    for (int c = 0; c < KRANGE / KC; ++c) {
        const int k0 = kbase + c * KC;

        // ---- stage x chunk: x[b][k0 .. k0+KC) -> xtile[b][.] ----
#pragma unroll
        for (int idx = tid; idx < BATCH * KC; idx += THREADS) {
            int b = idx >> 6;          // /KC
            int i = idx & (KC - 1);
            xtile[b * XSTRIDE + i] = x[b * IN_F + k0 + i];
        }

        // ---- dequant weights: OT outputs x KC k -> wtile ----
        // One 128-wide scale group covers the whole chunk (KC | GROUP).
#pragma unroll
        for (int idx = tid; idx < OT * (KC / 8); idx += THREADS) {
            int o = idx >> 3;          // output within tile
            int j = idx & 7;           // word within chunk
            int oglob = obase + o;
            int p = pw[oglob * (IN_F / 8) + (k0 >> 3) + j];
            float s = scale[oglob * (IN_F / GROUP) + (k0 >> 7)];
            float w[8];
#pragma unroll
            for (int e = 0; e < 8; ++e) {
                int wi = ((int)(((unsigned)p) << (28 - 4 * e))) >> 28;
                w[e] = (float)wi * s;
            }
            float4* dst = reinterpret_cast<float4*>(&wtile[o * KC + j * 8]);
            dst[0] = make_float4(w[0], w[1], w[2], w[3]);
            dst[1] = make_float4(w[4], w[5], w[6], w[7]);
        }
        __syncthreads();

        // ---- compute: per 4 k: 1 x-vec load + 8 broadcast w loads + 16 FFMA2
        const float* xrow = &xtile[lane * XSTRIDE];
        const float* wbase = &wtile[(warp * 8) * KC];
#pragma unroll
        for (int kk = 0; kk < KC; kk += 4) {
            ulonglong2 xv = *reinterpret_cast<const ulonglong2*>(&xrow[kk]);
#pragma unroll
            for (int oi = 0; oi < 8; ++oi) {
                ulonglong2 wv =
                    *reinterpret_cast<const ulonglong2*>(&wbase[oi * KC + kk]);
                fma2(accA[oi], wv.x, xv.x);
                fma2(accB[oi], wv.y, xv.y);
            }
        }
        __syncthreads();
    }

    // ---- epilogue: horizontal sum + atomic accumulate (KSPLIT partials) ----
    float* orow = &out[lane * OUT_F + obase + warp * 8];
#pragma unroll
    for (int oi = 0; oi < 8; ++oi) {
        atomicAdd(&orow[oi], hsum2(accA[oi]) + hsum2(accB[oi]));
    }
}

extern "C" void kernel_launch(void* const* d_in, const int* in_sizes, int n_in,
                              void* d_out, int out_size) {
    const float* x     = (const float*)d_in[0];
    const int*   pw    = (const int*)  d_in[1];
    const float* scale = (const float*)d_in[2];
    const float* bias  = (const float*)d_in[3];
    float* out = (float*)d_out;

    init_out_kernel<<<(BATCH * OUT_F + 255) / 256, 256>>>(bias, out);
    wql_kernel<<<OGROUPS * KSPLIT, THREADS>>>(x, pw, scale, out);
}

// round 2
// speedup vs baseline: 1.8866x; 1.8866x over previous
#include <cuda_runtime.h>
#include <cstdint>

#define OUT_F   11008
#define IN_F    4096
#define BATCH   32
#define GROUP   128

#define KC      128                 // k per smem stage (== GROUP: one scale/chunk)
#define KSPLIT  8
#define KRANGE  (IN_F / KSPLIT)     // 512
#define NCHUNK  (KRANGE / KC)       // 4
#define OB      128                 // outputs per block
#define OTILES  (OUT_F / OB)        // 86
#define THREADS 128
#define PWPITCH 17                  // padded row (words) for conflict-free reads

// Packed f32x2 FMA: d = a*b + d on two fp32 lanes.
__device__ __forceinline__ void fma2(unsigned long long &d,
                                     unsigned long long a,
                                     unsigned long long b) {
    asm("fma.rn.f32x2 %0, %1, %2, %0;" : "+l"(d) : "l"(a), "l"(b));
}

// duplicate scalar into both halves of an f32x2
__device__ __forceinline__ unsigned long long dup2(float w) {
    unsigned long long r;
    asm("mov.b64 %0, {%1, %1};" : "=l"(r) : "f"(w));
    return r;
}

__global__ void init_out_kernel(const float* __restrict__ bias,
                                float* __restrict__ out) {
    int i = blockIdx.x * blockDim.x + threadIdx.x;
    if (i < BATCH * OUT_F) out[i] = bias[i % OUT_F];
}

__global__ __launch_bounds__(THREADS)
void wql_kernel(const float* __restrict__ x,
                const int*   __restrict__ pw,
                const float* __restrict__ scale,
                float*       __restrict__ out) {
    __shared__ unsigned int pws[OB * PWPITCH];   // packed words, [o][w] padded
    __shared__ float        xT[KC * 32];         // x transposed [k][b], swizzled

    const int tid   = threadIdx.x;
    const int ot    = tid & 63;        // output-thread id (0..63)
    const int h     = tid >> 6;        // batch half (0,1) -> batch h*16..h*16+15
    const int obase = blockIdx.x * OB;
    const int ks    = blockIdx.y;
    const int o0    = obase + ot;      // this thread's 2 outputs
    const int o1    = obase + ot + 64;

    unsigned long long acc[2][8];      // [out][batch-pair] f32x2 accumulators
#pragma unroll
    for (int oi = 0; oi < 2; ++oi)
#pragma unroll
        for (int bp = 0; bp < 8; ++bp) acc[oi][bp] = 0ull;

    for (int c = 0; c < NCHUNK; ++c) {
        const int k0 = ks * KRANGE + c * KC;

        // ---- stage packed weights: OB rows x 16 words, coalesced ----
#pragma unroll 4
        for (int it = 0; it < 16; ++it) {
            int o = it * 8 + (tid >> 4);
            int w = tid & 15;
            pws[o * PWPITCH + w] =
                (unsigned int)pw[(obase + o) * (IN_F / 8) + (k0 >> 3) + w];
        }

        // ---- stage x transposed+swizzled: b = it, i = tid (coalesced reads) ----
#pragma unroll 4
        for (int b = 0; b < 32; ++b) {
            float v = x[b * IN_F + k0 + tid];
            int sw = tid * 32 + ((((b >> 2) + tid) & 7) << 2) + (b & 3);
            xT[sw] = v;
        }
        __syncthreads();

        const float s0 = scale[o0 * (IN_F / GROUP) + (k0 >> 7)];
        const float s1 = scale[o1 * (IN_F / GROUP) + (k0 >> 7)];

#pragma unroll 2
        for (int w = 0; w < 16; ++w) {
            const unsigned int p0 = pws[ot * PWPITCH + w];
            const unsigned int p1 = pws[(ot + 64) * PWPITCH + w];
#pragma unroll
            for (int e = 0; e < 8; ++e) {
                const int k = w * 8 + e;

                // dequant 2 weights in registers (arithmetic-shift sign extend)
                float w0 = (float)((int)(p0 << (28 - 4 * e)) >> 28) * s0;
                float w1 = (float)((int)(p1 << (28 - 4 * e)) >> 28) * s1;
                unsigned long long wp0 = dup2(w0);
                unsigned long long wp1 = dup2(w1);

                // 16 batch values for this k: 4 broadcast LDS.128
#pragma unroll
                for (int q = 0; q < 4; ++q) {
                    const int b4  = h * 4 + q;
                    const int off = k * 32 + (((b4 + k) & 7) << 2);
                    ulonglong2 xv =
                        *reinterpret_cast<const ulonglong2*>(&xT[off]);
                    fma2(acc[0][q * 2],     xv.x, wp0);
                    fma2(acc[0][q * 2 + 1], xv.y, wp0);
                    fma2(acc[1][q * 2],     xv.x, wp1);
                    fma2(acc[1][q * 2 + 1], xv.y, wp1);
                }
            }
        }
        __syncthreads();
    }

    // ---- epilogue: scatter partials (KSPLIT-way atomic accumulate) ----
#pragma unroll
    for (int oi = 0; oi < 2; ++oi) {
        const int o = (oi == 0) ? o0 : o1;
#pragma unroll
        for (int bp = 0; bp < 8; ++bp) {
            float lo, hi;
            asm("mov.b64 {%0, %1}, %2;" : "=f"(lo), "=f"(hi) : "l"(acc[oi][bp]));
            const int b = h * 16 + bp * 2;
            atomicAdd(&out[b * OUT_F + o], lo);
            atomicAdd(&out[(b + 1) * OUT_F + o], hi);
        }
    }
}

extern "C" void kernel_launch(void* const* d_in, const int* in_sizes, int n_in,
                              void* d_out, int out_size) {
    const float* x     = (const float*)d_in[0];
    const int*   pw    = (const int*)  d_in[1];
    const float* scale = (const float*)d_in[2];
    const float* bias  = (const float*)d_in[3];
    float* out = (float*)d_out;

    init_out_kernel<<<(BATCH * OUT_F + 255) / 256, 256>>>(bias, out);
    dim3 grid(OTILES, KSPLIT);
    wql_kernel<<<grid, THREADS>>>(x, pw, scale, out);
}

// round 5
// speedup vs baseline: 3.5778x; 1.8965x over previous
#include <cuda_runtime.h>
#include <cuda_bf16.h>
#include <cstdint>

#define OUT_F 11008
#define IN_F  4096
#define BATCH 32
#define GROUP 128

#define OB      128                 // M tile (outputs)
#define NB      64                  // N tile: cols 0-31 = x_hi, 32-63 = x_lo
#define OTILES  (OUT_F / OB)        // 86
#define KSPLIT  8
#define KRANGE  (IN_F / KSPLIT)     // 512
#define KC      64                  // k per smem chunk (2 chunks per quant group)
#define NCH     (KRANGE / KC)       // 8
#define THREADS 256
#define APITCH  72                  // bf16 elems per A row (144B, conflict-free LDSM)
#define BPITCH  72

__device__ __nv_bfloat16 g_xhl[2 * BATCH * IN_F];   // rows 0-31: x_hi, 32-63: x_lo

__device__ __forceinline__ uint32_t smem_u32(const void* p) {
    uint32_t a;
    asm("{ .reg .u64 t; cvta.to.shared.u64 t, %1; cvt.u32.u64 %0, t; }"
        : "=r"(a) : "l"(p));
    return a;
}
__device__ __forceinline__ void ldsm4(uint32_t& r0, uint32_t& r1, uint32_t& r2,
                                      uint32_t& r3, uint32_t addr) {
    asm volatile("ldmatrix.sync.aligned.m8n8.x4.shared.b16 {%0,%1,%2,%3}, [%4];"
                 : "=r"(r0), "=r"(r1), "=r"(r2), "=r"(r3) : "r"(addr));
}
__device__ __forceinline__ void mma_bf16(float& c0, float& c1, float& c2, float& c3,
                                         uint32_t a0, uint32_t a1, uint32_t a2,
                                         uint32_t a3, uint32_t b0, uint32_t b1) {
    asm volatile(
        "mma.sync.aligned.m16n8k16.row.col.f32.bf16.bf16.f32 "
        "{%0,%1,%2,%3}, {%4,%5,%6,%7}, {%8,%9}, {%0,%1,%2,%3};"
        : "+f"(c0), "+f"(c1), "+f"(c2), "+f"(c3)
        : "r"(a0), "r"(a1), "r"(a2), "r"(a3), "r"(b0), "r"(b1));
}

// ---------------- prep: x hi/lo split + out = bias ----------------
__global__ void prep_kernel(const float* __restrict__ x,
                            const float* __restrict__ bias,
                            float* __restrict__ out) {
    int i = blockIdx.x * blockDim.x + threadIdx.x;
    if (i < BATCH * IN_F) {
        float f = x[i];
        __nv_bfloat16 hi = __float2bfloat16(f);
        float lo = f - __bfloat162float(hi);
        int b = i >> 12;
        int k = i & (IN_F - 1);
        g_xhl[b * IN_F + k] = hi;
        g_xhl[(b + BATCH) * IN_F + k] = __float2bfloat16(lo);
    }
    if (i < BATCH * OUT_F) out[i] = bias[i % OUT_F];
}

// ---------------- main: HMMA bf16 GEMM ----------------
__global__ __launch_bounds__(THREADS)
void wql_hmma_kernel(const int*   __restrict__ pw,
                     const float* __restrict__ scale,
                     float*       __restrict__ out) {
    __shared__ __align__(16) __nv_bfloat16 smA[OB * APITCH];   // 18432 B
    __shared__ __align__(16) __nv_bfloat16 smB[NB * BPITCH];   //  9216 B

    const int tid   = threadIdx.x;
    const int wid   = tid >> 5;
    const int lane  = tid & 31;
    const int mwarp = wid & 3;          // 4 M-blocks of 32
    const int nwarp = wid >> 2;         // 0 = hi half, 1 = lo half
    const int obase = blockIdx.x * OB;
    const int ks    = blockIdx.y;
    const int kbase = ks * KRANGE;

    const uint32_t a_u32 = smem_u32(smA);
    const uint32_t b_u32 = smem_u32(smB);

    // ldmatrix source addresses (bytes), fixed per thread
    uint32_t aaddr[2], baddr[2];
#pragma unroll
    for (int mb = 0; mb < 2; ++mb)
        aaddr[mb] = a_u32 + (mwarp * 32 + mb * 16 + (lane & 15)) * (APITCH * 2)
                  + ((lane >> 4) & 1) * 16;
#pragma unroll
    for (int nb = 0; nb < 2; ++nb)
        baddr[nb] = b_u32 + (nwarp * 32 + nb * 16 + ((lane >> 4) & 1) * 8
                             + (lane & 7)) * (BPITCH * 2)
                  + ((lane >> 3) & 1) * 16;

    float pacc[2][4][4];   // persistent: [mb][n8-block][frag]
    float gacc[2][4][4];   // per-group partial (exact-int weights)
#pragma unroll
    for (int mb = 0; mb < 2; ++mb)
#pragma unroll
        for (int q = 0; q < 4; ++q)
#pragma unroll
            for (int j = 0; j < 4; ++j) { pacc[mb][q][j] = 0.f; gacc[mb][q][j] = 0.f; }

    const int pwrow = IN_F / 8;    // 512 words per output row

    for (int c = 0; c < NCH; ++c) {
        const int k0 = kbase + c * KC;
        if (c) __syncthreads();    // previous chunk fully consumed

        // ---- stage A: dequant int4 -> exact bf16 ----
#pragma unroll
        for (int it = 0; it < 4; ++it) {
            int idx = it * THREADS + tid;
            int row = idx >> 3;
            int w   = idx & 7;
            unsigned int p = (unsigned int)pw[(obase + row) * pwrow + (k0 >> 3) + w];
            uint32_t fb[8];
#pragma unroll
            for (int e = 0; e < 8; ++e) {
                int wi = ((int)(p << (28 - 4 * e))) >> 28;
                fb[e] = __float_as_uint((float)wi);      // bf16 = top 16 bits, exact
            }
            uint4 pk;
            pk.x = __byte_perm(fb[0], fb[1], 0x7632);
            pk.y = __byte_perm(fb[2], fb[3], 0x7632);
            pk.z = __byte_perm(fb[4], fb[5], 0x7632);
            pk.w = __byte_perm(fb[6], fb[7], 0x7632);
            *reinterpret_cast<uint4*>(&smA[row * APITCH + w * 8]) = pk;
        }

        // ---- stage B: x_hi/x_lo rows ----
#pragma unroll
        for (int it = 0; it < 2; ++it) {
            int idx = it * THREADS + tid;
            int row = idx >> 3;
            int seg = idx & 7;
            uint4 v = *reinterpret_cast<const uint4*>(&g_xhl[row * IN_F + k0 + seg * 8]);
            *reinterpret_cast<uint4*>(&smB[row * BPITCH + seg * 8]) = v;
        }
        __syncthreads();

        // ---- compute: 4 k16 steps ----
#pragma unroll
        for (int s = 0; s < 4; ++s) {
            uint32_t a[2][4], b[2][4];
            ldsm4(a[0][0], a[0][1], a[0][2], a[0][3], aaddr[0] + s * 32);
            ldsm4(a[1][0], a[1][1], a[1][2], a[1][3], aaddr[1] + s * 32);
            ldsm4(b[0][0], b[0][1], b[0][2], b[0][3], baddr[0] + s * 32);
            ldsm4(b[1][0], b[1][1], b[1][2], b[1][3], baddr[1] + s * 32);
#pragma unroll
            for (int mb = 0; mb < 2; ++mb)
#pragma unroll
                for (int q = 0; q < 4; ++q) {
                    mma_bf16(gacc[mb][q][0], gacc[mb][q][1],
                             gacc[mb][q][2], gacc[mb][q][3],
                             a[mb][0], a[mb][1], a[mb][2], a[mb][3],
                             b[q >> 1][(q & 1) * 2], b[q >> 1][(q & 1) * 2 + 1]);
                }
        }

        // ---- group boundary: scale partials into persistent acc ----
        if (c & 1) {
            const int gidx = ks * (KRANGE / GROUP) + (c >> 1);
#pragma unroll
            for (int mb = 0; mb < 2; ++mb) {
                const int r0 = obase + mwarp * 32 + mb * 16 + (lane >> 2);
                float s0 = __ldg(&scale[r0 * (IN_F / GROUP) + gidx]);
                float s1 = __ldg(&scale[(r0 + 8) * (IN_F / GROUP) + gidx]);
#pragma unroll
                for (int q = 0; q < 4; ++q) {
                    pacc[mb][q][0] = fmaf(gacc[mb][q][0], s0, pacc[mb][q][0]);
                    pacc[mb][q][1] = fmaf(gacc[mb][q][1], s0, pacc[mb][q][1]);
                    pacc[mb][q][2] = fmaf(gacc[mb][q][2], s1, pacc[mb][q][2]);
                    pacc[mb][q][3] = fmaf(gacc[mb][q][3], s1, pacc[mb][q][3]);
                    gacc[mb][q][0] = 0.f; gacc[mb][q][1] = 0.f;
                    gacc[mb][q][2] = 0.f; gacc[mb][q][3] = 0.f;
                }
            }
        }
    }

    // ---- epilogue: combine hi/lo halves, atomic accumulate ----
    float* red = reinterpret_cast<float*>(smA);   // [128][33]
    __syncthreads();
    if (nwarp == 1) {
#pragma unroll
        for (int mb = 0; mb < 2; ++mb) {
            const int m0 = mwarp * 32 + mb * 16 + (lane >> 2);
#pragma unroll
            for (int q = 0; q < 4; ++q) {
                const int bcol = q * 8 + (lane & 3) * 2;
                red[m0 * 33 + bcol]           = pacc[mb][q][0];
                red[m0 * 33 + bcol + 1]       = pacc[mb][q][1];
                red[(m0 + 8) * 33 + bcol]     = pacc[mb][q][2];
                red[(m0 + 8) * 33 + bcol + 1] = pacc[mb][q][3];
            }
        }
    }
    __syncthreads();
    if (nwarp == 0) {
#pragma unroll
        for (int mb = 0; mb < 2; ++mb) {
            const int m0 = mwarp * 32 + mb * 16 + (lane >> 2);
#pragma unroll
            for (int q = 0; q < 4; ++q) {
                const int bcol = q * 8 + (lane & 3) * 2;
                atomicAdd(&out[bcol * OUT_F + obase + m0],
                          pacc[mb][q][0] + red[m0 * 33 + bcol]);
                atomicAdd(&out[(bcol + 1) * OUT_F + obase + m0],
                          pacc[mb][q][1] + red[m0 * 33 + bcol + 1]);
                atomicAdd(&out[bcol * OUT_F + obase + m0 + 8],
                          pacc[mb][q][2] + red[(m0 + 8) * 33 + bcol]);
                atomicAdd(&out[(bcol + 1) * OUT_F + obase + m0 + 8],
                          pacc[mb][q][3] + red[(m0 + 8) * 33 + bcol + 1]);
            }
        }
    }
}

extern "C" void kernel_launch(void* const* d_in, const int* in_sizes, int n_in,
                              void* d_out, int out_size) {
    const float* x     = (const float*)d_in[0];
    const int*   pw    = (const int*)  d_in[1];
    const float* scale = (const float*)d_in[2];
    const float* bias  = (const float*)d_in[3];
    float* out = (float*)d_out;

    prep_kernel<<<(BATCH * OUT_F + 255) / 256, 256>>>(x, bias, out);
    dim3 grid(OTILES, KSPLIT);
    wql_hmma_kernel<<<grid, THREADS>>>(pw, scale, out);
}

// round 6
// speedup vs baseline: 4.0106x; 1.1209x over previous
#include <cuda_runtime.h>
#include <cuda_fp16.h>
#include <cstdint>

#define OUT_F 11008
#define IN_F  4096
#define BATCH 32
#define GROUP 128

#define OB      128                 // M tile (outputs)
#define NB      64                  // N tile: rows 0-31 x_hi, 32-63 x_lo
#define OTILES  (OUT_F / OB)        // 86
#define KSPLIT  8
#define KRANGE  (IN_F / KSPLIT)     // 512
#define KC      64                  // k per smem chunk (2 per quant group)
#define NCH     (KRANGE / KC)       // 8
#define THREADS 256
#define APITCH  72                  // f16 elems per row (144B: conflict-free LDSM)
#define BPITCH  72

// dynamic smem arena offsets (bytes)
#define SA0 0
#define SA1 18432
#define SB0 36864
#define SB1 46080
#define SMTOT 55296

#define DQ_MASK  0x000f000fu
#define DQ_MAGIC 0x64086408u        // fp16x2 (1032.0, 1032.0)

__device__ __half g_xhl[2 * BATCH * IN_F];   // rows 0-31: x_hi, 32-63: x_lo (k-permuted)

__device__ __forceinline__ uint32_t smem_u32(const void* p) {
    uint32_t a;
    asm("{ .reg .u64 t; cvta.to.shared.u64 t, %1; cvt.u32.u64 %0, t; }"
        : "=r"(a) : "l"(p));
    return a;
}
__device__ __forceinline__ void ldsm4(uint32_t& r0, uint32_t& r1, uint32_t& r2,
                                      uint32_t& r3, uint32_t addr) {
    asm volatile("ldmatrix.sync.aligned.m8n8.x4.shared.b16 {%0,%1,%2,%3}, [%4];"
                 : "=r"(r0), "=r"(r1), "=r"(r2), "=r"(r3) : "r"(addr));
}
__device__ __forceinline__ void mma_f16(float& c0, float& c1, float& c2, float& c3,
                                        uint32_t a0, uint32_t a1, uint32_t a2,
                                        uint32_t a3, uint32_t b0, uint32_t b1) {
    asm volatile(
        "mma.sync.aligned.m16n8k16.row.col.f32.f16.f16.f32 "
        "{%0,%1,%2,%3}, {%4,%5,%6,%7}, {%8,%9}, {%0,%1,%2,%3};"
        : "+f"(c0), "+f"(c1), "+f"(c2), "+f"(c3)
        : "r"(a0), "r"(a1), "r"(a2), "r"(a3), "r"(b0), "r"(b1));
}
__device__ __forceinline__ void cp16(uint32_t saddr, const void* gaddr) {
    asm volatile("cp.async.cg.shared.global [%0], [%1], 16;"
                 :: "r"(saddr), "l"(gaddr) : "memory");
}

// dequant one packed word -> 4 f16x2 regs (k-slots 2j,2j+1 hold nibbles j, j+4)
__device__ __forceinline__ void dq_word(uint32_t p, uint32_t w[4]) {
    const __half2 magic = *reinterpret_cast<const __half2*>(&(const uint32_t&)DQ_MAGIC);
#pragma unroll
    for (int j = 0; j < 4; ++j) {
        uint32_t r = ((p >> (4 * j)) & DQ_MASK) ^ DQ_MAGIC;
        __half2 h = __hsub2(*reinterpret_cast<__half2*>(&r), magic);
        w[j] = *reinterpret_cast<uint32_t*>(&h);
    }
}

// ---------------- prep: x hi/lo fp16 split (k-permuted) + out = bias ----------------
__global__ void prep_kernel(const float* __restrict__ x,
                            const float* __restrict__ bias,
                            float* __restrict__ out) {
    int i = blockIdx.x * blockDim.x + threadIdx.x;
    if (i < BATCH * IN_F) {
        float f = x[i];
        __half hi = __float2half_rn(f);
        __half lo = __float2half_rn(f - __half2float(hi));
        int b = i >> 12;
        int k = i & (IN_F - 1);
        int j = k & 7;
        int kp = (k & ~7) | ((j & 3) << 1) | (j >> 2);   // new pos of old j
        g_xhl[b * IN_F + kp] = hi;
        g_xhl[(b + BATCH) * IN_F + kp] = lo;
    }
    if (i < BATCH * OUT_F) out[i] = bias[i % OUT_F];
}

// ---------------- main: pipelined HMMA fp16 GEMM ----------------
__global__ __launch_bounds__(THREADS)
void wql_hmma_kernel(const int*   __restrict__ pw,
                     const float* __restrict__ scale,
                     float*       __restrict__ out) {
    extern __shared__ __align__(16) unsigned char dynsm[];
    const uint32_t smb = smem_u32(dynsm);

    const int tid   = threadIdx.x;
    const int wid   = tid >> 5;
    const int lane  = tid & 31;
    const int mwarp = wid & 3;
    const int nwarp = wid >> 2;          // 0 = hi half, 1 = lo half
    const int obase = blockIdx.x * OB;
    const int ks    = blockIdx.y;
    const int kbase = ks * KRANGE;
    const int pwrow = IN_F / 8;

    // staging roles
    const int arow = tid >> 1, aseg = tid & 1;            // A: 128 rows x 2 uint4
    const int brow = tid >> 3, bseg = tid & 7;            // B: per-iter 32 rows x 8 segs

    // ldsm per-thread offsets (bytes within a buffer)
    uint32_t aoff[2], boff[2];
#pragma unroll
    for (int mb = 0; mb < 2; ++mb)
        aoff[mb] = (mwarp * 32 + mb * 16 + (lane & 15)) * (APITCH * 2)
                 + ((lane >> 4) & 1) * 16;
#pragma unroll
    for (int nb = 0; nb < 2; ++nb)
        boff[nb] = (nwarp * 32 + nb * 16 + ((lane >> 4) & 1) * 8 + (lane & 7))
                 * (BPITCH * 2) + ((lane >> 3) & 1) * 16;

    const uint32_t abase[2] = { smb + SA0, smb + SA1 };
    const uint32_t bbase[2] = { smb + SB0, smb + SB1 };

    float pacc[2][4][4], gacc[2][4][4];
#pragma unroll
    for (int mb = 0; mb < 2; ++mb)
#pragma unroll
        for (int q = 0; q < 4; ++q)
#pragma unroll
            for (int j = 0; j < 4; ++j) { pacc[mb][q][j] = 0.f; gacc[mb][q][j] = 0.f; }

    // ---------- prologue: stage chunk 0 ----------
    uint4 pq = *reinterpret_cast<const uint4*>(
        &pw[(obase + arow) * pwrow + (kbase >> 3) + aseg * 4]);
#pragma unroll
    for (int it = 0; it < 2; ++it) {
        int r = it * 32 + brow;
        cp16(bbase[0] + r * (BPITCH * 2) + bseg * 16,
             &g_xhl[r * IN_F + kbase + bseg * 8]);
    }
    asm volatile("cp.async.commit_group;" ::: "memory");
    {
        uint32_t wv[4][4];
        dq_word(pq.x, wv[0]); dq_word(pq.y, wv[1]);
        dq_word(pq.z, wv[2]); dq_word(pq.w, wv[3]);
        uint32_t dst = abase[0] + arow * (APITCH * 2) + aseg * 64;
#pragma unroll
        for (int v = 0; v < 4; ++v)
            *reinterpret_cast<uint4*>(
                reinterpret_cast<unsigned char*>(dynsm) + (dst - smb) + v * 16) =
                make_uint4(wv[v][0], wv[v][1], wv[v][2], wv[v][3]);
    }

    for (int c = 0; c < NCH; ++c) {
        const int buf = c & 1;
        asm volatile("cp.async.wait_group 0;" ::: "memory");
        __syncthreads();                         // buf[c&1] ready everywhere

        // ---- prefetch chunk c+1 ----
        if (c + 1 < NCH) {
            const int k1 = kbase + (c + 1) * KC;
            pq = *reinterpret_cast<const uint4*>(
                &pw[(obase + arow) * pwrow + (k1 >> 3) + aseg * 4]);
#pragma unroll
            for (int it = 0; it < 2; ++it) {
                int r = it * 32 + brow;
                cp16(bbase[buf ^ 1] + r * (BPITCH * 2) + bseg * 16,
                     &g_xhl[r * IN_F + k1 + bseg * 8]);
            }
            asm volatile("cp.async.commit_group;" ::: "memory");
        }

        // ---- compute chunk c ----
#pragma unroll
        for (int s = 0; s < 4; ++s) {
            uint32_t a[2][4], b[2][4];
            ldsm4(a[0][0], a[0][1], a[0][2], a[0][3], abase[buf] + aoff[0] + s * 32);
            ldsm4(a[1][0], a[1][1], a[1][2], a[1][3], abase[buf] + aoff[1] + s * 32);
            ldsm4(b[0][0], b[0][1], b[0][2], b[0][3], bbase[buf] + boff[0] + s * 32);
            ldsm4(b[1][0], b[1][1], b[1][2], b[1][3], bbase[buf] + boff[1] + s * 32);
#pragma unroll
            for (int mb = 0; mb < 2; ++mb)
#pragma unroll
                for (int q = 0; q < 4; ++q)
                    mma_f16(gacc[mb][q][0], gacc[mb][q][1],
                            gacc[mb][q][2], gacc[mb][q][3],
                            a[mb][0], a[mb][1], a[mb][2], a[mb][3],
                            b[q >> 1][(q & 1) * 2], b[q >> 1][(q & 1) * 2 + 1]);
        }

        // ---- group boundary: fold scale ----
        if (c & 1) {
            const int gidx = ks * (KRANGE / GROUP) + (c >> 1);
#pragma unroll
            for (int mb = 0; mb < 2; ++mb) {
                const int r0 = obase + mwarp * 32 + mb * 16 + (lane >> 2);
                float s0 = __ldg(&scale[r0 * (IN_F / GROUP) + gidx]);
                float s1 = __ldg(&scale[(r0 + 8) * (IN_F / GROUP) + gidx]);
#pragma unroll
                for (int q = 0; q < 4; ++q) {
                    pacc[mb][q][0] = fmaf(gacc[mb][q][0], s0, pacc[mb][q][0]);
                    pacc[mb][q][1] = fmaf(gacc[mb][q][1], s0, pacc[mb][q][1]);
                    pacc[mb][q][2] = fmaf(gacc[mb][q][2], s1, pacc[mb][q][2]);
                    pacc[mb][q][3] = fmaf(gacc[mb][q][3], s1, pacc[mb][q][3]);
                    gacc[mb][q][0] = 0.f; gacc[mb][q][1] = 0.f;
                    gacc[mb][q][2] = 0.f; gacc[mb][q][3] = 0.f;
                }
            }
        }

        // ---- dequant chunk c+1 into the other buffer ----
        if (c + 1 < NCH) {
            uint32_t wv[4][4];
            dq_word(pq.x, wv[0]); dq_word(pq.y, wv[1]);
            dq_word(pq.z, wv[2]); dq_word(pq.w, wv[3]);
            uint32_t base = (buf ^ 1) ? SA1 : SA0;
            unsigned char* dst = reinterpret_cast<unsigned char*>(dynsm)
                               + base + arow * (APITCH * 2) + aseg * 64;
#pragma unroll
            for (int v = 0; v < 4; ++v)
                *reinterpret_cast<uint4*>(dst + v * 16) =
                    make_uint4(wv[v][0], wv[v][1], wv[v][2], wv[v][3]);
        }
    }

    // ---------- epilogue: combine hi/lo halves, atomic accumulate ----------
    float* red = reinterpret_cast<float*>(dynsm);   // [128][33] = 16896 B
    __syncthreads();
    if (nwarp == 1) {
#pragma unroll
        for (int mb = 0; mb < 2; ++mb) {
            const int m0 = mwarp * 32 + mb * 16 + (lane >> 2);
#pragma unroll
            for (int q = 0; q < 4; ++q) {
                const int bcol = q * 8 + (lane & 3) * 2;
                red[m0 * 33 + bcol]           = pacc[mb][q][0];
                red[m0 * 33 + bcol + 1]       = pacc[mb][q][1];
                red[(m0 + 8) * 33 + bcol]     = pacc[mb][q][2];
                red[(m0 + 8) * 33 + bcol + 1] = pacc[mb][q][3];
            }
        }
    }
    __syncthreads();
    if (nwarp == 0) {
#pragma unroll
        for (int mb = 0; mb < 2; ++mb) {
            const int m0 = mwarp * 32 + mb * 16 + (lane >> 2);
#pragma unroll
            for (int q = 0; q < 4; ++q) {
                const int bcol = q * 8 + (lane & 3) * 2;
                atomicAdd(&out[bcol * OUT_F + obase + m0],
                          pacc[mb][q][0] + red[m0 * 33 + bcol]);
                atomicAdd(&out[(bcol + 1) * OUT_F + obase + m0],
                          pacc[mb][q][1] + red[m0 * 33 + bcol + 1]);
                atomicAdd(&out[bcol * OUT_F + obase + m0 + 8],
                          pacc[mb][q][2] + red[(m0 + 8) * 33 + bcol]);
                atomicAdd(&out[(bcol + 1) * OUT_F + obase + m0 + 8],
                          pacc[mb][q][3] + red[(m0 + 8) * 33 + bcol + 1]);
            }
        }
    }
}

extern "C" void kernel_launch(void* const* d_in, const int* in_sizes, int n_in,
                              void* d_out, int out_size) {
    const float* x     = (const float*)d_in[0];
    const int*   pw    = (const int*)  d_in[1];
    const float* scale = (const float*)d_in[2];
    const float* bias  = (const float*)d_in[3];
    float* out = (float*)d_out;

    static int smem_set = 0;
    if (!smem_set) {
        cudaFuncSetAttribute(wql_hmma_kernel,
                             cudaFuncAttributeMaxDynamicSharedMemorySize, SMTOT);
        smem_set = 1;
    }

    prep_kernel<<<(BATCH * OUT_F + 255) / 256, 256>>>(x, bias, out);
    dim3 grid(OTILES, KSPLIT);
    wql_hmma_kernel<<<grid, THREADS, SMTOT>>>(pw, scale, out);
}

// round 7
// speedup vs baseline: 5.0625x; 1.2623x over previous
#include <cuda_runtime.h>
#include <cuda_fp16.h>
#include <cstdint>

#define OUT_F 11008
#define IN_F  4096
#define BATCH 32
#define GROUP 128

#define OB      128                  // M tile
#define OTILES  (OUT_F / OB)         // 86
#define KSPLIT  8
#define KRANGE  (IN_F / KSPLIT)      // 512
#define KC      128                  // k per chunk == GROUP (scale-rescale trick)
#define NCH     (KRANGE / KC)        // 4
#define THREADS 256
#define PWROW   (IN_F / 8)           // 512 words per output row

#define APITCH_B 80                  // A-packed row pitch (64B data + 16 pad)
#define BPITCH_B 272                 // B row pitch (256B data + 16 pad)

// smem arena (bytes)
#define SA0 0
#define SA1 10240
#define SB0 20480
#define SB1 37888
#define SMTOT 55296

#define DQ_MASK  0x000f000fu
#define DQ_MAGIC 0x64086408u         // fp16x2 (1032, 1032)

__device__ __half g_xhl[2 * BATCH * IN_F];   // rows 0-31: x_hi, 32-63: x_lo (k-permuted)

__device__ __forceinline__ uint32_t smem_u32(const void* p) {
    uint32_t a;
    asm("{ .reg .u64 t; cvta.to.shared.u64 t, %1; cvt.u32.u64 %0, t; }"
        : "=r"(a) : "l"(p));
    return a;
}
__device__ __forceinline__ void ldsm4(uint32_t& r0, uint32_t& r1, uint32_t& r2,
                                      uint32_t& r3, uint32_t addr) {
    asm volatile("ldmatrix.sync.aligned.m8n8.x4.shared.b16 {%0,%1,%2,%3}, [%4];"
                 : "=r"(r0), "=r"(r1), "=r"(r2), "=r"(r3) : "r"(addr));
}
__device__ __forceinline__ void lds64(uint32_t& lo, uint32_t& hi, uint32_t addr) {
    asm volatile("ld.shared.v2.u32 {%0,%1}, [%2];" : "=r"(lo), "=r"(hi) : "r"(addr));
}
__device__ __forceinline__ void mma_f16(float& c0, float& c1, float& c2, float& c3,
                                        uint32_t a0, uint32_t a1, uint32_t a2,
                                        uint32_t a3, uint32_t b0, uint32_t b1) {
    asm volatile(
        "mma.sync.aligned.m16n8k16.row.col.f32.f16.f16.f32 "
        "{%0,%1,%2,%3}, {%4,%5,%6,%7}, {%8,%9}, {%0,%1,%2,%3};"
        : "+f"(c0), "+f"(c1), "+f"(c2), "+f"(c3)
        : "r"(a0), "r"(a1), "r"(a2), "r"(a3), "r"(b0), "r"(b1));
}
__device__ __forceinline__ void cp16(uint32_t saddr, const void* gaddr) {
    asm volatile("cp.async.cg.shared.global [%0], [%1], 16;"
                 :: "r"(saddr), "l"(gaddr) : "memory");
}
// dequant: nibbles (c, c+4) of p -> f16x2 of exact signed int4 values
__device__ __forceinline__ uint32_t dqf(uint32_t p, int sh) {
    uint32_t r = ((p >> sh) & DQ_MASK) ^ DQ_MAGIC;
    const uint32_t mg = DQ_MAGIC;
    __half2 h = __hsub2(*reinterpret_cast<__half2*>(&r),
                        *reinterpret_cast<const __half2*>(&mg));
    return *reinterpret_cast<uint32_t*>(&h);
}

// ---------------- prep: x hi/lo fp16 split (k-permuted) + out = bias ----------------
__global__ void prep_kernel(const float* __restrict__ x,
                            const float* __restrict__ bias,
                            float* __restrict__ out) {
    int i = blockIdx.x * blockDim.x + threadIdx.x;
    if (i < BATCH * IN_F) {
        float f = x[i];
        __half hi = __float2half_rn(f);
        __half lo = __float2half_rn(f - __half2float(hi));
        int b = i >> 12;
        int k = i & (IN_F - 1);
        int j = k & 7;
        int kp = (k & ~7) | ((j & 3) << 1) | (j >> 2);   // nibble j -> k-slot
        g_xhl[b * IN_F + kp] = hi;
        g_xhl[(b + BATCH) * IN_F + kp] = lo;
    }
    if (i < BATCH * OUT_F) out[i] = bias[i % OUT_F];
}

// ---------------- main: register-dequant HMMA GEMM ----------------
__global__ __launch_bounds__(THREADS, 3)
void wql_hmma_kernel(const int*   __restrict__ pw,
                     const float* __restrict__ scale,
                     float*       __restrict__ out) {
    extern __shared__ __align__(16) unsigned char dynsm[];
    const uint32_t smb = smem_u32(dynsm);

    const int tid   = threadIdx.x;
    const int wid   = tid >> 5;
    const int lane  = tid & 31;
    const int obase = blockIdx.x * OB;
    const int ks    = blockIdx.y;
    const int kbase = ks * KRANGE;

    const int sh  = (lane & 3) * 4;          // dequant shift for this thread
    const int r0  = wid * 16 + (lane >> 2);  // A row (and r0+8)
    const uint32_t a0base = r0 * APITCH_B;
    const uint32_t a1base = (r0 + 8) * APITCH_B;

    uint32_t boff[4];
#pragma unroll
    for (int nb = 0; nb < 4; ++nb)
        boff[nb] = (nb * 16 + ((lane >> 4) & 1) * 8 + (lane & 7)) * BPITCH_B
                 + ((lane >> 3) & 1) * 16;

    const uint32_t ab[2] = { smb + SA0, smb + SA1 };
    const uint32_t bb[2] = { smb + SB0, smb + SB1 };

    // staging roles
    const int arow = tid >> 1, ahalf = tid & 1;   // A: 128 rows x 2x32B
    const int brow = tid >> 2, bq = tid & 3;      // B: 64 rows x 4x64B

    float pacc[8][4];
#pragma unroll
    for (int q = 0; q < 8; ++q)
#pragma unroll
        for (int j = 0; j < 4; ++j) pacc[q][j] = 0.f;

    // ---- stage chunk 0 ----
    {
        const int k0 = kbase;
        const int* asrc = &pw[(obase + arow) * PWROW + (k0 >> 3) + ahalf * 8];
        uint32_t adst = ab[0] + arow * APITCH_B + ahalf * 32;
        cp16(adst, asrc); cp16(adst + 16, asrc + 4);
        const __half* bsrc = &g_xhl[brow * IN_F + k0 + bq * 32];
        uint32_t bdst = bb[0] + brow * BPITCH_B + bq * 64;
#pragma unroll
        for (int v = 0; v < 4; ++v) cp16(bdst + v * 16, bsrc + v * 8);
        asm volatile("cp.async.commit_group;" ::: "memory");
    }

    float s_prev0 = 1.f, s_prev1 = 1.f;

    for (int c = 0; c < NCH; ++c) {
        const int buf = c & 1;
        asm volatile("cp.async.wait_group 0;" ::: "memory");
        __syncthreads();

        // ---- prefetch chunk c+1 ----
        if (c + 1 < NCH) {
            const int k1 = kbase + (c + 1) * KC;
            const int* asrc = &pw[(obase + arow) * PWROW + (k1 >> 3) + ahalf * 8];
            uint32_t adst = ab[buf ^ 1] + arow * APITCH_B + ahalf * 32;
            cp16(adst, asrc); cp16(adst + 16, asrc + 4);
            const __half* bsrc = &g_xhl[brow * IN_F + k1 + bq * 32];
            uint32_t bdst = bb[buf ^ 1] + brow * BPITCH_B + bq * 64;
#pragma unroll
            for (int v = 0; v < 4; ++v) cp16(bdst + v * 16, bsrc + v * 8);
            asm volatile("cp.async.commit_group;" ::: "memory");
        }

        // ---- rescale accumulators into this group's raw-int domain ----
        {
            const int gidx = ks * NCH + c;
            float s_cur0 = __ldg(&scale[(obase + r0) * (IN_F / GROUP) + gidx]);
            float s_cur1 = __ldg(&scale[(obase + r0 + 8) * (IN_F / GROUP) + gidx]);
            if (c) {
                float t0 = __fdividef(s_prev0, s_cur0);
                float t1 = __fdividef(s_prev1, s_cur1);
#pragma unroll
                for (int q = 0; q < 8; ++q) {
                    pacc[q][0] *= t0; pacc[q][1] *= t0;
                    pacc[q][2] *= t1; pacc[q][3] *= t1;
                }
            }
            s_prev0 = s_cur0; s_prev1 = s_cur1;
        }

        // ---- compute: 8 k16 steps, A dequant in registers ----
#pragma unroll
        for (int s = 0; s < 8; ++s) {
            uint32_t p0l, p0h, p1l, p1h;
            lds64(p0l, p0h, ab[buf] + a0base + s * 8);
            lds64(p1l, p1h, ab[buf] + a1base + s * 8);
            uint32_t a0 = dqf(p0l, sh), a2 = dqf(p0h, sh);
            uint32_t a1 = dqf(p1l, sh), a3 = dqf(p1h, sh);
#pragma unroll
            for (int nb = 0; nb < 4; ++nb) {
                uint32_t b0, b1, b2, b3;
                ldsm4(b0, b1, b2, b3, bb[buf] + boff[nb] + s * 32);
                mma_f16(pacc[2*nb][0], pacc[2*nb][1], pacc[2*nb][2], pacc[2*nb][3],
                        a0, a1, a2, a3, b0, b1);
                mma_f16(pacc[2*nb+1][0], pacc[2*nb+1][1], pacc[2*nb+1][2], pacc[2*nb+1][3],
                        a0, a1, a2, a3, b2, b3);
            }
        }
    }

    // ---- epilogue: apply final scale, combine hi/lo in-thread, atomics ----
    const int orow0 = obase + r0;
#pragma unroll
    for (int q = 0; q < 4; ++q) {
        const int bcol = q * 8 + (lane & 3) * 2;
        float v0 = (pacc[q][0] + pacc[q + 4][0]) * s_prev0;
        float v1 = (pacc[q][1] + pacc[q + 4][1]) * s_prev0;
        float v2 = (pacc[q][2] + pacc[q + 4][2]) * s_prev1;
        float v3 = (pacc[q][3] + pacc[q + 4][3]) * s_prev1;
        atomicAdd(&out[bcol * OUT_F + orow0], v0);
        atomicAdd(&out[(bcol + 1) * OUT_F + orow0], v1);
        atomicAdd(&out[bcol * OUT_F + orow0 + 8], v2);
        atomicAdd(&out[(bcol + 1) * OUT_F + orow0 + 8], v3);
    }
}

extern "C" void kernel_launch(void* const* d_in, const int* in_sizes, int n_in,
                              void* d_out, int out_size) {
    const float* x     = (const float*)d_in[0];
    const int*   pw    = (const int*)  d_in[1];
    const float* scale = (const float*)d_in[2];
    const float* bias  = (const float*)d_in[3];
    float* out = (float*)d_out;

    static int smem_set = 0;
    if (!smem_set) {
        cudaFuncSetAttribute(wql_hmma_kernel,
                             cudaFuncAttributeMaxDynamicSharedMemorySize, SMTOT);
        smem_set = 1;
    }

    prep_kernel<<<(BATCH * OUT_F + 255) / 256, 256>>>(x, bias, out);
    dim3 grid(OTILES, KSPLIT);
    wql_hmma_kernel<<<grid, THREADS, SMTOT>>>(pw, scale, out);
}

// round 8
// speedup vs baseline: 7.1817x; 1.4186x over previous
#include <cuda_runtime.h>
#include <cuda_fp16.h>
#include <cstdint>

#define OUT_F 11008
#define IN_F  4096
#define BATCH 32
#define GROUP 128

#define OB      128                  // M tile
#define OTILES  (OUT_F / OB)         // 86
#define KSPLIT  16
#define KRANGE  (IN_F / KSPLIT)      // 256
#define KC      128                  // chunk == GROUP (scale-rescale trick)
#define NCH     (KRANGE / KC)        // 2
#define THREADS 256
#define PWROW   (IN_F / 8)           // 512 words per output row

#define APITCH_B 80                  // A packed row pitch (64B data + 16 pad)
#define BPITCH_B 272                 // B row pitch (256B data + 16 pad)

// smem arena (bytes): A 2x10240, B 2x8704
#define SA0 0
#define SA1 10240
#define SB0 20480
#define SB1 29184
#define SMTOT 37888

#define DQ_MASK  0x000f000fu
#define DQ_MAGIC 0x64086408u         // fp16x2 (1032, 1032)

__device__ __half g_xh[BATCH * IN_F];    // x in fp16, k-permuted

__device__ __forceinline__ uint32_t smem_u32(const void* p) {
    uint32_t a;
    asm("{ .reg .u64 t; cvta.to.shared.u64 t, %1; cvt.u32.u64 %0, t; }"
        : "=r"(a) : "l"(p));
    return a;
}
__device__ __forceinline__ void ldsm4(uint32_t& r0, uint32_t& r1, uint32_t& r2,
                                      uint32_t& r3, uint32_t addr) {
    asm volatile("ldmatrix.sync.aligned.m8n8.x4.shared.b16 {%0,%1,%2,%3}, [%4];"
                 : "=r"(r0), "=r"(r1), "=r"(r2), "=r"(r3) : "r"(addr));
}
__device__ __forceinline__ void lds64(uint32_t& lo, uint32_t& hi, uint32_t addr) {
    asm volatile("ld.shared.v2.u32 {%0,%1}, [%2];" : "=r"(lo), "=r"(hi) : "r"(addr));
}
__device__ __forceinline__ void mma_f16(float& c0, float& c1, float& c2, float& c3,
                                        uint32_t a0, uint32_t a1, uint32_t a2,
                                        uint32_t a3, uint32_t b0, uint32_t b1) {
    asm volatile(
        "mma.sync.aligned.m16n8k16.row.col.f32.f16.f16.f32 "
        "{%0,%1,%2,%3}, {%4,%5,%6,%7}, {%8,%9}, {%0,%1,%2,%3};"
        : "+f"(c0), "+f"(c1), "+f"(c2), "+f"(c3)
        : "r"(a0), "r"(a1), "r"(a2), "r"(a3), "r"(b0), "r"(b1));
}
__device__ __forceinline__ void cp16(uint32_t saddr, const void* gaddr) {
    asm volatile("cp.async.cg.shared.global [%0], [%1], 16;"
                 :: "r"(saddr), "l"(gaddr) : "memory");
}
// nibbles (c, c+4) of p -> f16x2 of exact signed int4 values
__device__ __forceinline__ uint32_t dqf(uint32_t p, int sh) {
    uint32_t r = ((p >> sh) & DQ_MASK) ^ DQ_MAGIC;
    const uint32_t mg = DQ_MAGIC;
    __half2 h = __hsub2(*reinterpret_cast<__half2*>(&r),
                        *reinterpret_cast<const __half2*>(&mg));
    return *reinterpret_cast<uint32_t*>(&h);
}

// ---------------- prep: x fp16 (k-permuted) + out = bias ----------------
__global__ void prep_kernel(const float* __restrict__ x,
                            const float* __restrict__ bias,
                            float* __restrict__ out) {
    int i = blockIdx.x * blockDim.x + threadIdx.x;
    if (i < BATCH * IN_F) {
        int b = i >> 12;
        int k = i & (IN_F - 1);
        int j = k & 7;
        int kp = (k & ~7) | ((j & 3) << 1) | (j >> 2);   // nibble j -> k-slot
        g_xh[b * IN_F + kp] = __float2half_rn(x[i]);
    }
    if (i < BATCH * OUT_F) out[i] = bias[i % OUT_F];
}

// ---------------- main: register-dequant HMMA GEMM, N=32 ----------------
__global__ __launch_bounds__(THREADS, 4)
void wql_hmma_kernel(const int*   __restrict__ pw,
                     const float* __restrict__ scale,
                     float*       __restrict__ out) {
    extern __shared__ __align__(16) unsigned char dynsm[];
    const uint32_t smb = smem_u32(dynsm);

    const int tid   = threadIdx.x;
    const int wid   = tid >> 5;
    const int lane  = tid & 31;
    const int obase = blockIdx.x * OB;
    const int ks    = blockIdx.y;
    const int kbase = ks * KRANGE;

    const int sh  = (lane & 3) * 4;          // dequant shift
    const int r0  = wid * 16 + (lane >> 2);  // A rows r0, r0+8
    const uint32_t a0base = r0 * APITCH_B;
    const uint32_t a1base = (r0 + 8) * APITCH_B;

    uint32_t boff[2];
#pragma unroll
    for (int nb = 0; nb < 2; ++nb)
        boff[nb] = (nb * 16 + ((lane >> 4) & 1) * 8 + (lane & 7)) * BPITCH_B
                 + ((lane >> 3) & 1) * 16;

    const uint32_t ab[2] = { smb + SA0, smb + SA1 };
    const uint32_t bb[2] = { smb + SB0, smb + SB1 };

    // staging roles
    const int arow = tid >> 1, ahalf = tid & 1;   // A: 128 rows x 2x32B
    const int brow = tid >> 3, bseg = tid & 7;    // B: 32 rows x 8x32B

    float pacc[4][4];
#pragma unroll
    for (int q = 0; q < 4; ++q)
#pragma unroll
        for (int j = 0; j < 4; ++j) pacc[q][j] = 0.f;

    // ---- stage chunk 0 ----
    {
        const int* asrc = &pw[(obase + arow) * PWROW + (kbase >> 3) + ahalf * 8];
        uint32_t adst = ab[0] + arow * APITCH_B + ahalf * 32;
        cp16(adst, asrc); cp16(adst + 16, asrc + 4);
        const __half* bsrc = &g_xh[brow * IN_F + kbase + bseg * 16];
        uint32_t bdst = bb[0] + brow * BPITCH_B + bseg * 32;
        cp16(bdst, bsrc); cp16(bdst + 16, bsrc + 8);
        asm volatile("cp.async.commit_group;" ::: "memory");
    }

    float s_prev0 = 1.f, s_prev1 = 1.f;

#pragma unroll
    for (int c = 0; c < NCH; ++c) {
        const int buf = c & 1;
        asm volatile("cp.async.wait_group 0;" ::: "memory");
        __syncthreads();

        // ---- prefetch chunk c+1 ----
        if (c + 1 < NCH) {
            const int k1 = kbase + (c + 1) * KC;
            const int* asrc = &pw[(obase + arow) * PWROW + (k1 >> 3) + ahalf * 8];
            uint32_t adst = ab[buf ^ 1] + arow * APITCH_B + ahalf * 32;
            cp16(adst, asrc); cp16(adst + 16, asrc + 4);
            const __half* bsrc = &g_xh[brow * IN_F + k1 + bseg * 16];
            uint32_t bdst = bb[buf ^ 1] + brow * BPITCH_B + bseg * 32;
            cp16(bdst, bsrc); cp16(bdst + 16, bsrc + 8);
            asm volatile("cp.async.commit_group;" ::: "memory");
        }

        // ---- rescale accumulators into this group's raw-int domain ----
        {
            const int gidx = ks * NCH + c;
            float s_cur0 = __ldg(&scale[(obase + r0) * (IN_F / GROUP) + gidx]);
            float s_cur1 = __ldg(&scale[(obase + r0 + 8) * (IN_F / GROUP) + gidx]);
            if (c) {
                float t0 = __fdividef(s_prev0, s_cur0);
                float t1 = __fdividef(s_prev1, s_cur1);
#pragma unroll
                for (int q = 0; q < 4; ++q) {
                    pacc[q][0] *= t0; pacc[q][1] *= t0;
                    pacc[q][2] *= t1; pacc[q][3] *= t1;
                }
            }
            s_prev0 = s_cur0; s_prev1 = s_cur1;
        }

        // ---- compute: 8 k16 steps, A dequant in registers ----
#pragma unroll
        for (int s = 0; s < 8; ++s) {
            uint32_t p0l, p0h, p1l, p1h;
            lds64(p0l, p0h, ab[buf] + a0base + s * 8);
            lds64(p1l, p1h, ab[buf] + a1base + s * 8);
            uint32_t a0 = dqf(p0l, sh), a2 = dqf(p0h, sh);
            uint32_t a1 = dqf(p1l, sh), a3 = dqf(p1h, sh);
#pragma unroll
            for (int nb = 0; nb < 2; ++nb) {
                uint32_t b0, b1, b2, b3;
                ldsm4(b0, b1, b2, b3, bb[buf] + boff[nb] + s * 32);
                mma_f16(pacc[2*nb][0], pacc[2*nb][1], pacc[2*nb][2], pacc[2*nb][3],
                        a0, a1, a2, a3, b0, b1);
                mma_f16(pacc[2*nb+1][0], pacc[2*nb+1][1], pacc[2*nb+1][2], pacc[2*nb+1][3],
                        a0, a1, a2, a3, b2, b3);
            }
        }
    }

    // ---- epilogue: final scale + atomics ----
    const int orow0 = obase + r0;
#pragma unroll
    for (int q = 0; q < 4; ++q) {
        const int bcol = q * 8 + (lane & 3) * 2;
        atomicAdd(&out[bcol * OUT_F + orow0],           pacc[q][0] * s_prev0);
        atomicAdd(&out[(bcol + 1) * OUT_F + orow0],     pacc[q][1] * s_prev0);
        atomicAdd(&out[bcol * OUT_F + orow0 + 8],       pacc[q][2] * s_prev1);
        atomicAdd(&out[(bcol + 1) * OUT_F + orow0 + 8], pacc[q][3] * s_prev1);
    }
}

extern "C" void kernel_launch(void* const* d_in, const int* in_sizes, int n_in,
                              void* d_out, int out_size) {
    const float* x     = (const float*)d_in[0];
    const int*   pw    = (const int*)  d_in[1];
    const float* scale = (const float*)d_in[2];
    const float* bias  = (const float*)d_in[3];
    float* out = (float*)d_out;

    static int smem_set = 0;
    if (!smem_set) {
        cudaFuncSetAttribute(wql_hmma_kernel,
                             cudaFuncAttributeMaxDynamicSharedMemorySize, SMTOT);
        smem_set = 1;
    }

    prep_kernel<<<(BATCH * OUT_F + 255) / 256, 256>>>(x, bias, out);
    dim3 grid(OTILES, KSPLIT);
    wql_hmma_kernel<<<grid, THREADS, SMTOT>>>(pw, scale, out);
}